// round 3
// baseline (speedup 1.0000x reference)
#include <cuda_runtime.h>
#include <cstdint>

#define HH 128
#define WW 256
#define BB 8
#define HW (HH*WW)
#define NFUSED (BB*64*HH*WW)   // 16,777,216

constexpr int TW   = 64;    // tile width  (output cols per block)
constexpr int TH   = 8;     // tile height (output rows per block)
constexpr int CIB  = 8;     // input channels per chunk
constexpr int COT  = 16;    // output channels per block
constexpr int CP   = COT/2; // co pairs
constexpr int NTHR = 128;   // blockDim (32,4)
constexpr int TILE_ELEMS = CIB * 10 * 66;  // 5280 floats per input chunk

// Scratch activations (static device allocation — allowed)
__device__ float  g_h1 [BB*32*HW];
__device__ float  g_mid[BB*16*HW];
__device__ float  g_h2 [BB*32*HW];
__device__ double g_loss_acc;

__global__ void zero_loss_kernel() { g_loss_acc = 0.0; }

// ---- packed f32x2 helpers ------------------------------------------------
__device__ __forceinline__ unsigned long long dup2(float v) {
    unsigned long long r;
    asm("mov.b64 %0, {%1, %1};" : "=l"(r) : "f"(v));
    return r;
}
__device__ __forceinline__ unsigned long long ffma2(unsigned long long a,
                                                    unsigned long long b,
                                                    unsigned long long c) {
    unsigned long long d;
    asm("fma.rn.f32x2 %0, %1, %2, %3;" : "=l"(d) : "l"(a), "l"(b), "l"(c));
    return d;
}
__device__ __forceinline__ void unpack2(unsigned long long p, float& lo, float& hi) {
    asm("mov.b64 {%0, %1}, %2;" : "=f"(lo), "=f"(hi) : "l"(p));
}
__device__ __forceinline__ uint32_t s2u(const void* p) {
    return (uint32_t)__cvta_generic_to_shared(p);
}
__device__ __forceinline__ void cp_async4(uint32_t saddr, const void* gaddr, int srcsz) {
    asm volatile("cp.async.ca.shared.global [%0], [%1], 4, %2;"
                 :: "r"(saddr), "l"(gaddr), "r"(srcsz));
}
__device__ __forceinline__ void cp_commit() {
    asm volatile("cp.async.commit_group;" ::: "memory");
}
__device__ __forceinline__ void cp_wait1() {
    asm volatile("cp.async.wait_group 1;" ::: "memory");
}

// ---- direct 3x3 SAME conv + bias + ReLU, FFMA2 co-paired -----------------
// Block: tile 64x8 pixels, 16 output channels. Grid z = b * (CO/16) + co_chunk.
// If LOSS: accumulate sum((ref - out)^2) into g_loss_acc instead of writing.
template<int CI, int CO, bool LOSS>
__global__ void __launch_bounds__(NTHR, 4)
conv3x3_kernel(const float* __restrict__ in,
               const float* __restrict__ wgt,
               const float* __restrict__ bias,
               float* __restrict__ out,
               const float* __restrict__ ref)
{
    __shared__ float  s_in[2][CIB][10][66];
    __shared__ float2 s_w [2][CIB][9][CP];

    const int tx  = threadIdx.x;           // 0..31
    const int ty  = threadIdx.y;           // 0..3
    const int tid = ty*32 + tx;
    const int x0  = blockIdx.x * TW;
    const int y0  = blockIdx.y * TH;
    constexpr int ZCO = CO / COT;
    const int b   = blockIdx.z / ZCO;
    const int co0 = (blockIdx.z % ZCO) * COT;
    const float* inb = in + (size_t)b*CI*HW;

    constexpr int NC = CI / CIB;

    // acc[pair j][pixel p], pixels: 0=(ty,tx) 1=(ty,tx+32) 2=(ty+4,tx) 3=(ty+4,tx+32)
    unsigned long long acc[CP][4];
#pragma unroll
    for (int j = 0; j < CP; j++)
#pragma unroll
        for (int p = 0; p < 4; p++) acc[j][p] = 0ull;

    auto stage = [&](int chunk, int buf) {
        // input tile chunk via cp.async (zfill halo)
        const float* src0 = inb + (size_t)chunk*CIB*HW;
        uint32_t sbase = s2u(&s_in[buf][0][0][0]);
        for (int i = tid; i < TILE_ELEMS; i += NTHR) {
            int ci = i / 660; int r = i - ci*660;
            int yy = r / 66;  int xx = r - yy*66;
            int gy = y0 + yy - 1, gx = x0 + xx - 1;
            bool ok = ((unsigned)gy < HH) & ((unsigned)gx < WW);
            const float* g = ok ? (src0 + ci*HW + gy*WW + gx) : src0;
            cp_async4(sbase + i*4, g, ok ? 4 : 0);
        }
        // weights, co-paired: s_w[ci][k][j] = (w[co0+2j], w[co0+2j+1])
        for (int i = tid; i < CIB*9*CP*2; i += NTHR) {
            int h = i & 1; int p = i >> 1;
            int j = p % CP; int q = p / CP;    // q = ci*9 + k
            int k = q % 9;  int ci = q / 9;
            int co = co0 + 2*j + h;
            ((float*)&s_w[buf][ci][k][j])[h] =
                wgt[((size_t)co*CI + chunk*CIB + ci)*9 + k];
        }
    };

    stage(0, 0);
    cp_commit();

#pragma unroll 1
    for (int c = 0; c < NC; c++) {
        const int buf = c & 1;
        if (c + 1 < NC) stage(c + 1, buf ^ 1);
        cp_commit();
        cp_wait1();
        __syncthreads();

#pragma unroll 2
        for (int ci = 0; ci < CIB; ci++) {
#pragma unroll
            for (int dy = 0; dy < 3; dy++) {
                const float* r0 = &s_in[buf][ci][ty + dy    ][tx];
                const float* r1 = &s_in[buf][ci][ty + dy + 4][tx];
                unsigned long long v0 = dup2(r0[0]),  v1 = dup2(r0[1]),  v2 = dup2(r0[2]);
                unsigned long long v3 = dup2(r0[32]), v4 = dup2(r0[33]), v5 = dup2(r0[34]);
                unsigned long long v6 = dup2(r1[0]),  v7 = dup2(r1[1]),  v8 = dup2(r1[2]);
                unsigned long long v9 = dup2(r1[32]), va = dup2(r1[33]), vb = dup2(r1[34]);
                const unsigned long long* w0p =
                    (const unsigned long long*)&s_w[buf][ci][dy*3 + 0][0];
                const unsigned long long* w1p =
                    (const unsigned long long*)&s_w[buf][ci][dy*3 + 1][0];
                const unsigned long long* w2p =
                    (const unsigned long long*)&s_w[buf][ci][dy*3 + 2][0];
#pragma unroll
                for (int j = 0; j < CP; j++) {
                    unsigned long long w0 = w0p[j], w1 = w1p[j], w2 = w2p[j];
                    acc[j][0] = ffma2(v0, w0, acc[j][0]);
                    acc[j][0] = ffma2(v1, w1, acc[j][0]);
                    acc[j][0] = ffma2(v2, w2, acc[j][0]);
                    acc[j][1] = ffma2(v3, w0, acc[j][1]);
                    acc[j][1] = ffma2(v4, w1, acc[j][1]);
                    acc[j][1] = ffma2(v5, w2, acc[j][1]);
                    acc[j][2] = ffma2(v6, w0, acc[j][2]);
                    acc[j][2] = ffma2(v7, w1, acc[j][2]);
                    acc[j][2] = ffma2(v8, w2, acc[j][2]);
                    acc[j][3] = ffma2(v9, w0, acc[j][3]);
                    acc[j][3] = ffma2(va, w1, acc[j][3]);
                    acc[j][3] = ffma2(vb, w2, acc[j][3]);
                }
            }
        }
        __syncthreads();
    }

    // epilogue: bias + relu, then store or loss
    float lsum = 0.f;
#pragma unroll
    for (int j = 0; j < CP; j++) {
        float blo = __ldg(&bias[co0 + 2*j]);
        float bhi = __ldg(&bias[co0 + 2*j + 1]);
        size_t chlo = ((size_t)b*CO + co0 + 2*j) * HW;
#pragma unroll
        for (int p = 0; p < 4; p++) {
            int row = y0 + ty + (p >> 1)*4;
            int col = x0 + tx + (p & 1)*32;
            size_t idx = chlo + (size_t)row*WW + col;
            float alo, ahi;
            unpack2(acc[j][p], alo, ahi);
            float olo = fmaxf(alo + blo, 0.f);
            float ohi = fmaxf(ahi + bhi, 0.f);
            if (LOSS) {
                float dlo = ref[idx]      - olo;
                float dhi = ref[idx + HW] - ohi;
                lsum += dlo*dlo + dhi*dhi;
            } else {
                out[idx]      = olo;
                out[idx + HW] = ohi;
            }
        }
    }

    if (LOSS) {
#pragma unroll
        for (int off = 16; off > 0; off >>= 1)
            lsum += __shfl_down_sync(0xffffffffu, lsum, off);
        __shared__ float s_red[4];
        if ((tid & 31) == 0) s_red[tid >> 5] = lsum;
        __syncthreads();
        if (tid == 0)
            atomicAdd(&g_loss_acc,
                      (double)(s_red[0] + s_red[1] + s_red[2] + s_red[3]));
    }
}

// fused_feat = 0.5*(feat0 + feat1)  (exact algebraic reduction of the
// cross-modal attention: second-stage logits are identical across m, so
// softmax over m is exactly 0.5 each).
__global__ void fuse_avg_kernel(const float4* __restrict__ a,
                                const float4* __restrict__ b,
                                float4* __restrict__ o, int n4)
{
    int i = blockIdx.x * blockDim.x + threadIdx.x;
    if (i < n4) {
        float4 x = a[i], y = b[i];
        o[i] = make_float4(0.5f*(x.x+y.x), 0.5f*(x.y+y.y),
                           0.5f*(x.z+y.z), 0.5f*(x.w+y.w));
    }
}

__global__ void finalize_kernel(float* out, int begin, int end)
{
    float loss = (float)(g_loss_acc * (1.0 / (double)NFUSED));
    for (int i = begin + (int)threadIdx.x; i < end; i += (int)blockDim.x)
        out[i] = loss;
}

extern "C" void kernel_launch(void* const* d_in, const int* in_sizes, int n_in,
                              void* d_out, int out_size)
{
    const float* feat0 = (const float*)d_in[0];
    const float* feat1 = (const float*)d_in[1];
    const float* w1 = (const float*)d_in[2];  const float* b1 = (const float*)d_in[3];
    const float* w2 = (const float*)d_in[4];  const float* b2 = (const float*)d_in[5];
    const float* w3 = (const float*)d_in[6];  const float* b3 = (const float*)d_in[7];
    const float* w4 = (const float*)d_in[8];  const float* b4 = (const float*)d_in[9];
    float* out = (float*)d_out;

    float *h1, *mid, *h2;
    cudaGetSymbolAddress((void**)&h1,  g_h1);
    cudaGetSymbolAddress((void**)&mid, g_mid);
    cudaGetSymbolAddress((void**)&h2,  g_h2);

    dim3 blk(32, 4);
    dim3 g1(4, 16, BB * (32/COT));   // conv1: 64 -> 32
    dim3 g2(4, 16, BB * (16/COT==0?1:16/COT));  // conv2: 32 -> 16 (ZCO=1)
    dim3 g3(4, 16, BB * (32/COT));   // conv3: 16 -> 32
    dim3 g4(4, 16, BB * (64/COT));   // conv4: 32 -> 64 (+loss)

    zero_loss_kernel<<<1, 1>>>();

    const float* feats[2] = {feat0, feat1};
    for (int m = 0; m < 2; m++) {
        const float* f = feats[m];
        conv3x3_kernel<64, 32, false><<<g1, blk>>>(f,   w1, b1, h1,  nullptr);
        conv3x3_kernel<32, 16, false><<<g2, blk>>>(h1,  w2, b2, mid, nullptr);
        conv3x3_kernel<16, 32, false><<<g3, blk>>>(mid, w3, b3, h2,  nullptr);
        conv3x3_kernel<32, 64, true ><<<g4, blk>>>(h2,  w4, b4, nullptr, f);
    }

    // fused_feat = average of the two modalities
    int n4 = NFUSED / 4;
    fuse_avg_kernel<<<(n4 + 255) / 256, 256>>>(
        (const float4*)feat0, (const float4*)feat1, (float4*)out, n4);

    // auto_enc_loss goes after the fused tensor in the flattened output
    if (out_size > NFUSED)
        finalize_kernel<<<1, 32>>>(out, NFUSED, out_size);
}

// round 5
// speedup vs baseline: 4.1881x; 4.1881x over previous
#include <cuda_runtime.h>
#include <cuda_bf16.h>
#include <cstdint>

#define HH 128
#define WW 256
#define BB 8
#define HW (HH*WW)
#define NFUSED (BB*64*HW)
#define YP 130
#define XP 258
#define PS (YP*XP*16)     // elems per 16-channel padded plane

// static device scratch (allowed)
__device__ __align__(128) __nv_bfloat16 g_x0[BB*4*PS];
__device__ __align__(128) __nv_bfloat16 g_x1[BB*4*PS];
__device__ __align__(128) __nv_bfloat16 g_h1[BB*2*PS];
__device__ __align__(128) __nv_bfloat16 g_md[BB*1*PS];
__device__ __align__(128) __nv_bfloat16 g_h2[BB*2*PS];
__device__ __align__(128) __nv_bfloat16 g_wb[46080];
__device__ double g_loss;

// ---- helpers -------------------------------------------------------------
__device__ __forceinline__ uint32_t s2u(const void* p){return (uint32_t)__cvta_generic_to_shared(p);}
__device__ __forceinline__ void cpa16(uint32_t s, const void* g){
  asm volatile("cp.async.cg.shared.global [%0],[%1],16;"::"r"(s),"l"(g));}
__device__ __forceinline__ void cpacommit(){asm volatile("cp.async.commit_group;":::"memory");}
__device__ __forceinline__ void cpawait0(){asm volatile("cp.async.wait_group 0;":::"memory");}
__device__ __forceinline__ void cpawait1(){asm volatile("cp.async.wait_group 1;":::"memory");}

// ---- small kernels -------------------------------------------------------
__global__ void zero_loss_k(){ g_loss = 0.0; }

__global__ void pad_zero(__nv_bfloat16* p){
  size_t base = (size_t)blockIdx.y*PS;
  const int tot = (2*XP + 2*YP)*16;
  for (int k = blockIdx.x*blockDim.x + threadIdx.x; k < tot; k += gridDim.x*blockDim.x){
    size_t e;
    if (k < XP*16) e = k;
    else if (k < 2*XP*16) e = (size_t)129*XP*16 + (k - XP*16);
    else if (k < (2*XP+YP)*16) { int z = k - 2*XP*16; e = (size_t)(z>>4)*XP*16 + (z&15); }
    else { int z = k - (2*XP+YP)*16; e = (size_t)(z>>4)*XP*16 + 257*16 + (z&15); }
    p[base+e] = __float2bfloat16(0.f);
  }
}

// weights: g_wb[off + ((tap*NCH+kc)*CO + co)*16 + q] = w[co][kc*16+q][tap]
__global__ void prep_w(const float* w1,const float* w2,const float* w3,const float* w4){
  int i = blockIdx.x*blockDim.x + threadIdx.x;
  int co,ci,off; const float* w;
  if (i < 18432)      { co=32; ci=64; off=0;     w=w1; }
  else if (i < 23040) { co=16; ci=32; off=18432; w=w2; }
  else if (i < 27648) { co=32; ci=16; off=23040; w=w3; }
  else if (i < 46080) { co=64; ci=32; off=27648; w=w4; }
  else return;
  int r = i - off;
  int q = r & 15; int r2 = r >> 4;
  int c = r2 % co; int r3 = r2 / co;
  int nch = ci/16;
  int kc = r3 % nch; int t = r3 / nch;
  g_wb[i] = __float2bfloat16(w[((size_t)c*ci + kc*16 + q)*9 + t]);
}

// fp32 NCHW feats -> exact fused avg (fp32, d_out) + padded chunked NHWC bf16
__global__ void __launch_bounds__(64)
conv_fuse(const float4* __restrict__ f0, const float4* __restrict__ f1,
          float4* __restrict__ out,
          __nv_bfloat16* __restrict__ x0, __nv_bfloat16* __restrict__ x1)
{
  const int xq = threadIdx.x, y = blockIdx.y, b = blockIdx.z;
  for (int cc = 0; cc < 4; cc++) {
    uint32_t oa[4][8], ob[4][8];
#pragma unroll
    for (int h = 0; h < 8; h++) {
      size_t i0 = ((size_t)(b*64 + cc*16 + 2*h)*HH + y)*(WW/4) + xq;
      size_t i1 = i0 + (size_t)HH*(WW/4);
      float4 a0 = f0[i0], a1 = f0[i1], v0 = f1[i0], v1 = f1[i1];
      out[i0] = make_float4(.5f*(a0.x+v0.x), .5f*(a0.y+v0.y), .5f*(a0.z+v0.z), .5f*(a0.w+v0.w));
      out[i1] = make_float4(.5f*(a1.x+v1.x), .5f*(a1.y+v1.y), .5f*(a1.z+v1.z), .5f*(a1.w+v1.w));
      const float* pa0=(const float*)&a0; const float* pa1=(const float*)&a1;
      const float* pv0=(const float*)&v0; const float* pv1=(const float*)&v1;
#pragma unroll
      for (int p = 0; p < 4; p++) {
        asm("cvt.rn.bf16x2.f32 %0,%1,%2;":"=r"(oa[p][h]):"f"(pa1[p]),"f"(pa0[p]));
        asm("cvt.rn.bf16x2.f32 %0,%1,%2;":"=r"(ob[p][h]):"f"(pv1[p]),"f"(pv0[p]));
      }
    }
#pragma unroll
    for (int p = 0; p < 4; p++) {
      int x = xq*4 + p;
      size_t di = (size_t)(b*4+cc)*PS + ((size_t)(y+1)*XP + (x+1))*16;
      uint4* da = (uint4*)(x0 + di); uint4* db = (uint4*)(x1 + di);
      da[0] = make_uint4(oa[p][0],oa[p][1],oa[p][2],oa[p][3]);
      da[1] = make_uint4(oa[p][4],oa[p][5],oa[p][6],oa[p][7]);
      db[0] = make_uint4(ob[p][0],ob[p][1],ob[p][2],ob[p][3]);
      db[1] = make_uint4(ob[p][4],ob[p][5],ob[p][6],ob[p][7]);
    }
  }
}

__global__ void finalize_k(float* out, int n){
  float l = (float)(g_loss * (1.0/(double)NFUSED));
  for (int i = NFUSED + (int)threadIdx.x; i < n; i += (int)blockDim.x) out[i] = l;
}

// ---- mma.sync conv: 9 shift-GEMMs, warp-level HMMA -----------------------
// CTA: 256 thr = 8 warps; tile 8 rows x 64 cols; warp w = row w (M=64).
// A tile smem: [10][66][16] bf16 per chunk buffer (21120 B), double buffered.
constexpr int AB    = 21120;
constexpr int WOFFS = 2*AB;      // 42240

template<int NCH,int COT,int N,bool LOSS>
__global__ void __launch_bounds__(256,2)
conv_mma(const __nv_bfloat16* __restrict__ in, const __nv_bfloat16* __restrict__ wq,
         const float* __restrict__ bias, __nv_bfloat16* __restrict__ outp,
         const float* __restrict__ ref)
{
  extern __shared__ __align__(1024) char smem[];
  const int tid = threadIdx.x, lane = tid & 31, w = tid >> 5;
  constexpr int ZCO = COT/N;
  constexpr int NC8 = N/8;
  const int b = blockIdx.z/ZCO, co0 = (blockIdx.z%ZCO)*N;
  const int x0 = blockIdx.x*64, y0 = blockIdx.y*8;
  uint32_t sb = s2u(smem);

  // stage this CTA's co-slice of weights: [9][NCH][N][16] bf16
  constexpr int WUNITS = 9*NCH*N*2;
  for (int i = tid; i < WUNITS; i += 256) {
    int blk = i/(2*N), rem = i%(2*N);
    cpa16(sb + WOFFS + i*16, (const char*)wq + ((size_t)blk*COT + co0)*32 + rem*16);
  }
  const char* inb = (const char*)in + (size_t)b*NCH*PS*2 + ((size_t)y0*XP + x0)*32;
  auto stagein = [&](int c){
    const char* src = inb + (size_t)c*PS*2;
    uint32_t dst = sb + (c&1)*AB;
    for (int i = tid; i < 1320; i += 256) {
      int r = i/132, u = i - r*132;
      cpa16(dst + i*16, src + (size_t)r*XP*32 + u*16);
    }
  };
  stagein(0); cpacommit();

  float acc[4][NC8][4];
#pragma unroll
  for (int mc=0;mc<4;mc++)
#pragma unroll
    for (int nc=0;nc<NC8;nc++)
#pragma unroll
      for (int k=0;k<4;k++) acc[mc][nc][k]=0.f;

  const int l4 = lane >> 2, q4 = lane & 3;
  const uint32_t aLane = sb + (w*66 + (lane & 15))*32 + (lane >> 4)*16;
  const uint32_t wLane = sb + WOFFS + l4*32 + q4*4;

  for (int c = 0; c < NCH; c++) {
    if (c + 1 < NCH) { stagein(c+1); cpacommit(); cpawait1(); }
    else             { cpawait0(); }
    __syncthreads();
    uint32_t aBuf = aLane + (c&1)*AB;
#pragma unroll
    for (int t = 0; t < 9; t++) {
      uint32_t brow = wLane + (uint32_t)((t*NCH + c)*N)*32;
      uint32_t bf[NC8][2];
#pragma unroll
      for (int nc = 0; nc < NC8; nc++) {
        asm("ld.shared.b32 %0,[%1];" : "=r"(bf[nc][0]) : "r"(brow + nc*256));
        asm("ld.shared.b32 %0,[%1];" : "=r"(bf[nc][1]) : "r"(brow + nc*256 + 16));
      }
      uint32_t aTap = aBuf + (uint32_t)((t/3)*66 + (t%3))*32;
#pragma unroll
      for (int mc = 0; mc < 4; mc++) {
        uint32_t a0,a1,a2,a3;
        asm volatile("ldmatrix.sync.aligned.m8n8.x4.shared.b16 {%0,%1,%2,%3},[%4];"
          : "=r"(a0),"=r"(a1),"=r"(a2),"=r"(a3) : "r"(aTap + mc*512));
#pragma unroll
        for (int nc = 0; nc < NC8; nc++) {
          asm("mma.sync.aligned.m16n8k16.row.col.f32.bf16.bf16.f32 "
              "{%0,%1,%2,%3},{%4,%5,%6,%7},{%8,%9},{%0,%1,%2,%3};"
              : "+f"(acc[mc][nc][0]),"+f"(acc[mc][nc][1]),
                "+f"(acc[mc][nc][2]),"+f"(acc[mc][nc][3])
              : "r"(a0),"r"(a1),"r"(a2),"r"(a3),"r"(bf[nc][0]),"r"(bf[nc][1]));
        }
      }
    }
    __syncthreads();
  }

  // epilogue
  const int y = y0 + w;
  float lsum = 0.f;
#pragma unroll
  for (int nc = 0; nc < NC8; nc++) {
    int ch = co0 + nc*8 + q4*2;
    float bv0 = __ldg(&bias[ch]), bv1 = __ldg(&bias[ch+1]);
#pragma unroll
    for (int mc = 0; mc < 4; mc++) {
#pragma unroll
      for (int h = 0; h < 2; h++) {
        int x = x0 + mc*16 + l4 + h*8;
        float f0v = fmaxf(acc[mc][nc][2*h]   + bv0, 0.f);
        float f1v = fmaxf(acc[mc][nc][2*h+1] + bv1, 0.f);
        if (LOSS) {
          const float* rp = ref + ((size_t)(b*64 + ch)*HH + y)*WW + x;
          float d0 = rp[0]  - f0v;
          float d1 = rp[HW] - f1v;
          lsum += d0*d0 + d1*d1;
        } else {
          uint32_t pk;
          asm("cvt.rn.bf16x2.f32 %0,%1,%2;" : "=r"(pk) : "f"(f1v), "f"(f0v));
          size_t idx = (size_t)(b*(COT/16) + (ch >> 4))*PS
                     + ((size_t)(y+1)*XP + (x+1))*16 + (ch & 15);
          *(uint32_t*)(outp + idx) = pk;
        }
      }
    }
  }

  if (LOSS) {
#pragma unroll
    for (int off = 16; off; off >>= 1) lsum += __shfl_down_sync(~0u, lsum, off);
    __shared__ float sr[8];
    if (lane == 0) sr[w] = lsum;
    __syncthreads();
    if (tid == 0) {
      float s = 0.f;
#pragma unroll
      for (int i = 0; i < 8; i++) s += sr[i];
      atomicAdd(&g_loss, (double)s);
    }
  }
}

// ---- launch --------------------------------------------------------------
extern "C" void kernel_launch(void* const* d_in, const int* in_sizes, int n_in,
                              void* d_out, int out_size)
{
  const float* f0 = (const float*)d_in[0];
  const float* f1 = (const float*)d_in[1];
  const float* w1 = (const float*)d_in[2];  const float* b1 = (const float*)d_in[3];
  const float* w2 = (const float*)d_in[4];  const float* b2 = (const float*)d_in[5];
  const float* w3 = (const float*)d_in[6];  const float* b3 = (const float*)d_in[7];
  const float* w4 = (const float*)d_in[8];  const float* b4 = (const float*)d_in[9];
  float* out = (float*)d_out;

  __nv_bfloat16 *x0,*x1,*h1,*md,*h2,*wb;
  cudaGetSymbolAddress((void**)&x0, g_x0);
  cudaGetSymbolAddress((void**)&x1, g_x1);
  cudaGetSymbolAddress((void**)&h1, g_h1);
  cudaGetSymbolAddress((void**)&md, g_md);
  cudaGetSymbolAddress((void**)&h2, g_h2);
  cudaGetSymbolAddress((void**)&wb, g_wb);

  const int smem1 = WOFFS + 9*4*32*32;  // 79104
  const int smem2 = WOFFS + 9*2*16*32;  // 51456
  const int smem3 = WOFFS + 9*1*32*32;  // 51456
  const int smem4 = WOFFS + 9*2*32*32;  // 60672
  cudaFuncSetAttribute(conv_mma<4,32,32,false>, cudaFuncAttributeMaxDynamicSharedMemorySize, smem1);
  cudaFuncSetAttribute(conv_mma<2,16,16,false>, cudaFuncAttributeMaxDynamicSharedMemorySize, smem2);
  cudaFuncSetAttribute(conv_mma<1,32,32,false>, cudaFuncAttributeMaxDynamicSharedMemorySize, smem3);
  cudaFuncSetAttribute(conv_mma<2,64,32,true >, cudaFuncAttributeMaxDynamicSharedMemorySize, smem4);

  zero_loss_k<<<1,1>>>();
  pad_zero<<<dim3(4, BB*4), 256>>>(x0);
  pad_zero<<<dim3(4, BB*4), 256>>>(x1);
  pad_zero<<<dim3(4, BB*2), 256>>>(h1);
  pad_zero<<<dim3(4, BB*1), 256>>>(md);
  pad_zero<<<dim3(4, BB*2), 256>>>(h2);
  prep_w<<<(46080+255)/256, 256>>>(w1, w2, w3, w4);
  conv_fuse<<<dim3(1, HH, BB), 64>>>((const float4*)f0, (const float4*)f1,
                                     (float4*)out, x0, x1);
  dim3 cg(4, 16, BB);
  for (int m = 0; m < 2; m++) {
    const __nv_bfloat16* xin = m ? x1 : x0;
    const float* fr = m ? f1 : f0;
    conv_mma<4,32,32,false><<<cg, 256, smem1>>>(xin, wb+0,     b1, h1, nullptr);
    conv_mma<2,16,16,false><<<cg, 256, smem2>>>(h1,  wb+18432, b2, md, nullptr);
    conv_mma<1,32,32,false><<<cg, 256, smem3>>>(md,  wb+23040, b3, h2, nullptr);
    conv_mma<2,64,32,true ><<<dim3(4,16,BB*2), 256, smem4>>>(h2, wb+27648, b4, nullptr, fr);
  }
  if (out_size > NFUSED) finalize_k<<<1,32>>>(out, out_size);
}

// round 6
// speedup vs baseline: 5.2474x; 1.2529x over previous
#include <cuda_runtime.h>
#include <cuda_bf16.h>
#include <cstdint>

#define HH 128
#define WW 256
#define BB 8
#define HW (HH*WW)
#define NFUSED (BB*64*HW)
#define YP 130
#define XP 258
#define PS (YP*XP*16)        // elems per 16-channel padded plane (536640)

// modality strides (elems)
#define X_MS  ((size_t)BB*4*PS)
#define H1_MS ((size_t)BB*2*PS)
#define MD_MS ((size_t)BB*1*PS)
#define H2_MS ((size_t)BB*2*PS)

// static device scratch (allowed)
__device__ __align__(128) __nv_bfloat16 g_x [2*BB*4*PS];
__device__ __align__(128) __nv_bfloat16 g_h1[2*BB*2*PS];
__device__ __align__(128) __nv_bfloat16 g_md[2*BB*1*PS];
__device__ __align__(128) __nv_bfloat16 g_h2[2*BB*2*PS];
__device__ __align__(128) __nv_bfloat16 g_wb[46080];
__device__ double g_loss;

// ---- helpers -------------------------------------------------------------
__device__ __forceinline__ uint32_t s2u(const void* p){return (uint32_t)__cvta_generic_to_shared(p);}
__device__ __forceinline__ void cpa16(uint32_t s, const void* g){
  asm volatile("cp.async.cg.shared.global [%0],[%1],16;"::"r"(s),"l"(g));}
__device__ __forceinline__ void cpacommit(){asm volatile("cp.async.commit_group;":::"memory");}
__device__ __forceinline__ void cpawait0(){asm volatile("cp.async.wait_group 0;":::"memory");}
__device__ __forceinline__ void cpawait1(){asm volatile("cp.async.wait_group 1;":::"memory");}

// ---- small kernels -------------------------------------------------------
__global__ void zero_loss_k(){ g_loss = 0.0; }

// zero borders of every padded plane across all scratch buffers (one launch)
__global__ void pad_all(__nv_bfloat16* px, __nv_bfloat16* ph1,
                        __nv_bfloat16* pmd, __nv_bfloat16* ph2){
  int pid = blockIdx.y;
  __nv_bfloat16* p;
  if      (pid < 64)       p = px  + (size_t)pid*PS;
  else if (pid < 96)       p = ph1 + (size_t)(pid-64)*PS;
  else if (pid < 112)      p = pmd + (size_t)(pid-96)*PS;
  else                     p = ph2 + (size_t)(pid-112)*PS;
  const int tot = (2*XP + 2*YP)*16;
  for (int k = blockIdx.x*blockDim.x + threadIdx.x; k < tot; k += gridDim.x*blockDim.x){
    size_t e;
    if (k < XP*16) e = k;
    else if (k < 2*XP*16) e = (size_t)129*XP*16 + (k - XP*16);
    else if (k < (2*XP+YP)*16) { int z = k - 2*XP*16; e = (size_t)(z>>4)*XP*16 + (z&15); }
    else { int z = k - (2*XP+YP)*16; e = (size_t)(z>>4)*XP*16 + 257*16 + (z&15); }
    p[e] = __float2bfloat16(0.f);
  }
}

// weights: g_wb[off + ((tap*NCH+kc)*CO + co)*16 + q] = w[co][kc*16+q][tap]
__global__ void prep_w(const float* w1,const float* w2,const float* w3,const float* w4){
  int i = blockIdx.x*blockDim.x + threadIdx.x;
  int co,ci,off; const float* w;
  if (i < 18432)      { co=32; ci=64; off=0;     w=w1; }
  else if (i < 23040) { co=16; ci=32; off=18432; w=w2; }
  else if (i < 27648) { co=32; ci=16; off=23040; w=w3; }
  else if (i < 46080) { co=64; ci=32; off=27648; w=w4; }
  else return;
  int r = i - off;
  int q = r & 15; int r2 = r >> 4;
  int c = r2 % co; int r3 = r2 / co;
  int nch = ci/16;
  int kc = r3 % nch; int t = r3 / nch;
  g_wb[i] = __float2bfloat16(w[((size_t)c*ci + kc*16 + q)*9 + t]);
}

// fp32 NCHW feats -> exact fused avg (fp32, d_out) + padded chunked NHWC bf16
__global__ void __launch_bounds__(64)
conv_fuse(const float4* __restrict__ f0, const float4* __restrict__ f1,
          float4* __restrict__ out, __nv_bfloat16* __restrict__ xb)
{
  const int xq = threadIdx.x, y = blockIdx.y, b = blockIdx.z;
  for (int cc = 0; cc < 4; cc++) {
    uint32_t oa[4][8], ob[4][8];
#pragma unroll
    for (int h = 0; h < 8; h++) {
      size_t i0 = ((size_t)(b*64 + cc*16 + 2*h)*HH + y)*(WW/4) + xq;
      size_t i1 = i0 + (size_t)HH*(WW/4);
      float4 a0 = f0[i0], a1 = f0[i1], v0 = f1[i0], v1 = f1[i1];
      out[i0] = make_float4(.5f*(a0.x+v0.x), .5f*(a0.y+v0.y), .5f*(a0.z+v0.z), .5f*(a0.w+v0.w));
      out[i1] = make_float4(.5f*(a1.x+v1.x), .5f*(a1.y+v1.y), .5f*(a1.z+v1.z), .5f*(a1.w+v1.w));
      const float* pa0=(const float*)&a0; const float* pa1=(const float*)&a1;
      const float* pv0=(const float*)&v0; const float* pv1=(const float*)&v1;
#pragma unroll
      for (int p = 0; p < 4; p++) {
        asm("cvt.rn.bf16x2.f32 %0,%1,%2;":"=r"(oa[p][h]):"f"(pa1[p]),"f"(pa0[p]));
        asm("cvt.rn.bf16x2.f32 %0,%1,%2;":"=r"(ob[p][h]):"f"(pv1[p]),"f"(pv0[p]));
      }
    }
#pragma unroll
    for (int p = 0; p < 4; p++) {
      int x = xq*4 + p;
      size_t di = (size_t)(b*4+cc)*PS + ((size_t)(y+1)*XP + (x+1))*16;
      uint4* da = (uint4*)(xb + di); uint4* db = (uint4*)(xb + X_MS + di);
      da[0] = make_uint4(oa[p][0],oa[p][1],oa[p][2],oa[p][3]);
      da[1] = make_uint4(oa[p][4],oa[p][5],oa[p][6],oa[p][7]);
      db[0] = make_uint4(ob[p][0],ob[p][1],ob[p][2],ob[p][3]);
      db[1] = make_uint4(ob[p][4],ob[p][5],ob[p][6],ob[p][7]);
    }
  }
}

__global__ void finalize_k(float* out, int n){
  float l = (float)(g_loss * (1.0/(double)NFUSED));
  for (int i = NFUSED + (int)threadIdx.x; i < n; i += (int)blockDim.x) out[i] = l;
}

// ---- mma.sync conv: 9 shift-GEMMs, warp-level HMMA -----------------------
// CTA: 256 thr = 8 warps; tile 8 rows x 64 cols; warp w = row w (M=64).
// A tile smem: [10 rows][66 px] with 48B pixel stride (conflict-free ldmatrix).
constexpr int PXS   = 48;          // padded pixel stride bytes
constexpr int ROWS_ = 66*PXS;      // 3168
constexpr int AB    = 10*ROWS_;    // 31680
constexpr int WOFFS = 2*AB;        // 63360

template<int NCH,int COT,int N,bool LOSS>
__global__ void __launch_bounds__(256,2)
conv_mma(const __nv_bfloat16* __restrict__ in, size_t in_ms,
         const __nv_bfloat16* __restrict__ wq, const float* __restrict__ bias,
         __nv_bfloat16* __restrict__ outp, size_t out_ms,
         const __nv_bfloat16* __restrict__ ref, size_t ref_ms)
{
  extern __shared__ __align__(1024) char smem[];
  const int tid = threadIdx.x, lane = tid & 31, w = tid >> 5;
  constexpr int ZCO = COT/N;
  constexpr int NC8 = N/8;
  const int zz = blockIdx.z;
  const int m = zz / (BB*ZCO);
  const int zr = zz - m*(BB*ZCO);
  const int b = zr/ZCO, co0 = (zr%ZCO)*N;
  const int x0 = blockIdx.x*64, y0 = blockIdx.y*8;
  uint32_t sb = s2u(smem);

  // stage this CTA's co-slice of weights: [9][NCH][N][16] bf16
  constexpr int WUNITS = 9*NCH*N*2;
  for (int i = tid; i < WUNITS; i += 256) {
    int blk = i/(2*N), rem = i%(2*N);
    cpa16(sb + WOFFS + i*16, (const char*)wq + ((size_t)blk*COT + co0)*32 + rem*16);
  }
  const char* inb = (const char*)(in + m*in_ms) + (size_t)b*NCH*PS*2
                    + ((size_t)y0*XP + x0)*32;
  auto stagein = [&](int c){
    const char* src = inb + (size_t)c*PS*2;
    uint32_t dst = sb + (c&1)*AB;
    for (int i = tid; i < 1320; i += 256) {
      int px = i >> 1, half = i & 1;
      int r = px/66, u = px - r*66;
      cpa16(dst + (r*66+u)*PXS + half*16, src + (size_t)r*XP*32 + u*32 + half*16);
    }
  };
  stagein(0); cpacommit();

  float acc[4][NC8][4];
#pragma unroll
  for (int mc=0;mc<4;mc++)
#pragma unroll
    for (int nc=0;nc<NC8;nc++)
#pragma unroll
      for (int k=0;k<4;k++) acc[mc][nc][k]=0.f;

  const int l4 = lane >> 2, q4 = lane & 3;
  const uint32_t aLane = sb + w*ROWS_ + (lane & 15)*PXS + (lane >> 4)*16;
  const uint32_t wLane = sb + WOFFS + l4*32 + q4*4;

  for (int c = 0; c < NCH; c++) {
    if (c + 1 < NCH) { stagein(c+1); cpacommit(); cpawait1(); }
    else             { cpawait0(); }
    __syncthreads();
    uint32_t aBuf = aLane + (c&1)*AB;
#pragma unroll
    for (int t = 0; t < 9; t++) {
      uint32_t brow = wLane + (uint32_t)((t*NCH + c)*N)*32;
      uint32_t bf[NC8][2];
#pragma unroll
      for (int nc = 0; nc < NC8; nc++) {
        asm("ld.shared.b32 %0,[%1];" : "=r"(bf[nc][0]) : "r"(brow + nc*256));
        asm("ld.shared.b32 %0,[%1];" : "=r"(bf[nc][1]) : "r"(brow + nc*256 + 16));
      }
      uint32_t aTap = aBuf + (uint32_t)((t/3)*66 + (t%3))*PXS;
#pragma unroll
      for (int mc = 0; mc < 4; mc++) {
        uint32_t a0,a1,a2,a3;
        asm volatile("ldmatrix.sync.aligned.m8n8.x4.shared.b16 {%0,%1,%2,%3},[%4];"
          : "=r"(a0),"=r"(a1),"=r"(a2),"=r"(a3) : "r"(aTap + mc*16*PXS));
#pragma unroll
        for (int nc = 0; nc < NC8; nc++) {
          asm("mma.sync.aligned.m16n8k16.row.col.f32.bf16.bf16.f32 "
              "{%0,%1,%2,%3},{%4,%5,%6,%7},{%8,%9},{%0,%1,%2,%3};"
              : "+f"(acc[mc][nc][0]),"+f"(acc[mc][nc][1]),
                "+f"(acc[mc][nc][2]),"+f"(acc[mc][nc][3])
              : "r"(a0),"r"(a1),"r"(a2),"r"(a3),"r"(bf[nc][0]),"r"(bf[nc][1]));
        }
      }
    }
    __syncthreads();
  }

  // epilogue
  const int y = y0 + w;
  float lsum = 0.f;
#pragma unroll
  for (int nc = 0; nc < NC8; nc++) {
    int ch = co0 + nc*8 + q4*2;
    float bv0 = __ldg(&bias[ch]), bv1 = __ldg(&bias[ch+1]);
#pragma unroll
    for (int mc = 0; mc < 4; mc++) {
#pragma unroll
      for (int h = 0; h < 2; h++) {
        int x = x0 + mc*16 + l4 + h*8;
        float f0v = fmaxf(acc[mc][nc][2*h]   + bv0, 0.f);
        float f1v = fmaxf(acc[mc][nc][2*h+1] + bv1, 0.f);
        if (LOSS) {
          // bf16 padded-NHWC ref (same layout as conv inputs)
          size_t ri = m*ref_ms + (size_t)(b*4 + (ch >> 4))*PS
                    + ((size_t)(y+1)*XP + (x+1))*16 + (ch & 15);
          uint32_t rv = *(const uint32_t*)(ref + ri);
          float r0 = __bfloat162float(*(const __nv_bfloat16*)&rv);
          float r1 = __bfloat162float(*((const __nv_bfloat16*)&rv + 1));
          float d0 = r0 - f0v, d1 = r1 - f1v;
          lsum += d0*d0 + d1*d1;
        } else {
          uint32_t pk;
          asm("cvt.rn.bf16x2.f32 %0,%1,%2;" : "=r"(pk) : "f"(f1v), "f"(f0v));
          size_t idx = m*out_ms + (size_t)(b*(COT/16) + (ch >> 4))*PS
                     + ((size_t)(y+1)*XP + (x+1))*16 + (ch & 15);
          *(uint32_t*)(outp + idx) = pk;
        }
      }
    }
  }

  if (LOSS) {
#pragma unroll
    for (int off = 16; off; off >>= 1) lsum += __shfl_down_sync(~0u, lsum, off);
    __shared__ float sr[8];
    if (lane == 0) sr[w] = lsum;
    __syncthreads();
    if (tid == 0) {
      float s = 0.f;
#pragma unroll
      for (int i = 0; i < 8; i++) s += sr[i];
      atomicAdd(&g_loss, (double)s);
    }
  }
}

// ---- launch --------------------------------------------------------------
extern "C" void kernel_launch(void* const* d_in, const int* in_sizes, int n_in,
                              void* d_out, int out_size)
{
  const float* f0 = (const float*)d_in[0];
  const float* f1 = (const float*)d_in[1];
  const float* w1 = (const float*)d_in[2];  const float* b1 = (const float*)d_in[3];
  const float* w2 = (const float*)d_in[4];  const float* b2 = (const float*)d_in[5];
  const float* w3 = (const float*)d_in[6];  const float* b3 = (const float*)d_in[7];
  const float* w4 = (const float*)d_in[8];  const float* b4 = (const float*)d_in[9];
  float* out = (float*)d_out;

  __nv_bfloat16 *xb,*h1,*md,*h2,*wb;
  cudaGetSymbolAddress((void**)&xb, g_x);
  cudaGetSymbolAddress((void**)&h1, g_h1);
  cudaGetSymbolAddress((void**)&md, g_md);
  cudaGetSymbolAddress((void**)&h2, g_h2);
  cudaGetSymbolAddress((void**)&wb, g_wb);

  const int smem1 = WOFFS + 9*4*32*32;  // 100224
  const int smem2 = WOFFS + 9*2*16*32;  // 72576
  const int smem3 = WOFFS + 9*1*32*32;  // 72576
  const int smem4 = WOFFS + 9*2*32*32;  // 81792
  cudaFuncSetAttribute(conv_mma<4,32,32,false>, cudaFuncAttributeMaxDynamicSharedMemorySize, smem1);
  cudaFuncSetAttribute(conv_mma<2,16,16,false>, cudaFuncAttributeMaxDynamicSharedMemorySize, smem2);
  cudaFuncSetAttribute(conv_mma<1,32,32,false>, cudaFuncAttributeMaxDynamicSharedMemorySize, smem3);
  cudaFuncSetAttribute(conv_mma<2,64,32,true >, cudaFuncAttributeMaxDynamicSharedMemorySize, smem4);

  zero_loss_k<<<1,1>>>();
  pad_all<<<dim3(4,144), 256>>>(xb, h1, md, h2);
  prep_w<<<(46080+255)/256, 256>>>(w1, w2, w3, w4);
  conv_fuse<<<dim3(1, HH, BB), 64>>>((const float4*)f0, (const float4*)f1,
                                     (float4*)out, xb);
  // both modalities per launch: grid.z = 2 * BB * ZCO
  conv_mma<4,32,32,false><<<dim3(4,16,2*BB),   256, smem1>>>(xb, X_MS,  wb+0,     b1, h1, H1_MS, nullptr, 0);
  conv_mma<2,16,16,false><<<dim3(4,16,2*BB),   256, smem2>>>(h1, H1_MS, wb+18432, b2, md, MD_MS, nullptr, 0);
  conv_mma<1,32,32,false><<<dim3(4,16,2*BB),   256, smem3>>>(md, MD_MS, wb+23040, b3, h2, H2_MS, nullptr, 0);
  conv_mma<2,64,32,true ><<<dim3(4,16,2*BB*2), 256, smem4>>>(h2, H2_MS, wb+27648, b4, nullptr, 0, xb, X_MS);
  if (out_size > NFUSED) finalize_k<<<1,32>>>(out, out_size);
}